// round 2
// baseline (speedup 1.0000x reference)
#include <cuda_runtime.h>
#include <math.h>

#define Lt   2097153
#define NF   4194304
#define NH   2097152
#define L1n  1048577
#define L2n  524289
#define L3n  262145
#define NB3  4097

__device__ float2 g_A[NF];
__device__ float2 g_B[NF];
__device__ float  g_base[Lt];
__device__ float  g_h1[33554464];
__device__ float  g_h2[33554496];
__device__ float  g_part3[NB3 * 128];
__device__ float  g_progpart[1024];
__device__ float  g_prog_mean;
__device__ float  g_feat[128];
__device__ int    g_ws[40], g_we[40], g_wh[40], g_wk[40];
__device__ float  g_wcoef[40];
__device__ int    g_nw, g_wmax;

__global__ void k_prep(const float* __restrict__ z) {
    int i = blockIdx.x * 256 + threadIdx.x;
    g_A[i] = make_float2(i < Lt ? z[i] : 0.0f, 0.0f);
}

__global__ void k_fft(int srcA, int logs, float sign, float inv2m) {
    const float2* __restrict__ x = srcA ? g_A : g_B;
    float2* __restrict__ y = srcA ? g_B : g_A;
    int idx = blockIdx.x * 256 + threadIdx.x;
    int s_ = 1 << logs, p = idx >> logs, q = idx & (s_ - 1);
    float2 a = x[q + s_ * p], b = x[q + s_ * p + NH];
    float ang = sign * 6.2831853071795864f * ((float)p * inv2m);
    float sn, cs; sincosf(ang, &sn, &cs);
    float dx = a.x - b.x, dy = a.y - b.y;
    int ya = q + ((s_ * p) << 1);
    y[ya]      = make_float2(a.x + b.x, a.y + b.y);
    y[ya + s_] = make_float2(dx * cs - dy * sn, dx * sn + dy * cs);
}

__global__ void k_prog(const float* __restrict__ w1, const float* __restrict__ b1,
                       const float* __restrict__ w2, const float* __restrict__ b2,
                       const float* __restrict__ w3, const float* __restrict__ b3,
                       const float* __restrict__ harm) {
    __shared__ float sw1[32], sb1[32], sw2[512], sb2[16], sw3[16], shr[8], sred[256];
    int tid = threadIdx.x;
    if (tid < 32) { sw1[tid] = w1[tid]; sb1[tid] = b1[tid]; }
    if (tid < 16) { sb2[tid] = b2[tid]; sw3[tid] = w3[tid * 8 + 1]; }
    for (int i = tid; i < 512; i += 256) sw2[i] = w2[i];
    if (tid < 8) shr[tid] = harm[tid*4] + harm[tid*4+1] + harm[tid*4+2] + harm[tid*4+3];
    __syncthreads();
    float b3_1 = b3[1], acc = 0.0f;
    for (int t = blockIdx.x * 256 + tid; t < Lt; t += 1024 * 256) {
        float tf = (float)t, tn = tf / 2097153.0f;
        float h1r[32];
        #pragma unroll
        for (int j = 0; j < 32; j++) h1r[j] = fmaxf(tn * sw1[j] + sb1[j], 0.0f);
        float mp1 = b3_1;
        #pragma unroll 4
        for (int k = 0; k < 16; k++) {
            float a2 = sb2[k];
            #pragma unroll
            for (int j = 0; j < 32; j++) a2 += h1r[j] * sw2[j * 16 + k];
            mp1 += fmaxf(a2, 0.0f) * sw3[k];
        }
        float sv = 1.0f + mp1 * sinf((6.2831853071795864f * tf) / 2097153.0f);
        int idx = ((int)floorf((tf / 2097153.0f) * 8.0f)) % 8;
        acc += sv * shr[idx];
    }
    sred[tid] = acc; __syncthreads();
    for (int s = 128; s > 0; s >>= 1) { if (tid < s) sred[tid] += sred[tid + s]; __syncthreads(); }
    if (tid == 0) g_progpart[blockIdx.x] = sred[0];
}

__global__ void k_progfinal() {
    __shared__ double sd[256];
    int tid = threadIdx.x; double a = 0.0;
    for (int i = tid; i < 1024; i += 256) a += (double)g_progpart[i];
    sd[tid] = a; __syncthreads();
    for (int s = 128; s > 0; s >>= 1) { if (tid < s) sd[tid] += sd[tid + s]; __syncthreads(); }
    if (tid == 0) g_prog_mean = (float)(sd[0] / (4.0 * 2097153.0));
}

__global__ void k_wininit() {
    const double SPECd[8] = {7.83, 528.0, 396.0, 2.5, 14.1, 432.0, 6.0, 30.0};
    const double val = 1.0 / (4194304.0 * (1.0 / 22050.0));
    int n = 0, wmax = 0;
    for (int k = 0; k < 8; k++)
        for (int m = 1; m <= 5; m++) {
            double hf = SPECd[k] * m;
            if (hf >= 11025.0) continue;
            int i0 = (int)floor(hf / val + 0.5);
            int best = -1; double bd = 1e300;
            for (int i = i0 - 2; i <= i0 + 2; i++) {
                if (i < 0) continue;
                float fr = (float)((double)i * val);
                double d = fabs((double)fr - hf);
                if (d < bd) { bd = d; best = i; }
            }
            int s = best - 15; if (s < 0) s = 0;
            int e = best + 15; if (e > Lt - 1) e = Lt - 1;
            g_ws[n] = s; g_we[n] = e; g_wh[n] = best; g_wk[n] = k;
            g_wcoef[n] = (float)(1.0 / pow((double)m, 1.2));
            if (e > wmax) wmax = e;
            n++;
        }
    g_nw = n; g_wmax = wmax;
}

__global__ void k_passA(const float* __restrict__ band_w, const float* __restrict__ freq_w) {
    int k = blockIdx.x * 256 + threadIdx.x;
    if (k >= Lt) return;
    float kf = (float)k;
    float f = (float)((double)k * (1.0 / (4194304.0 * (1.0 / 22050.0))));
    float M = 1.0f;
    const float lo[6] = {1.f, 4.f, 8.f, 13.f, 30.f, 100.f};
    const float hi[6] = {4.f, 8.f, 13.f, 30.f, 100.f, 200.f};
    if (f <= 200.0f) {
        #pragma unroll
        for (int b = 0; b < 6; b++)
            if (f >= lo[b] && f <= hi[b]) {
                float c = (lo[b] + hi[b]) * 0.5f, hw = (hi[b] - lo[b]) * 0.25f;
                float d = (f - c) / hw;
                float mask = expf(-0.5f * d * d);
                float ab = (float)(6.283185307179586 * (double)c);
                float tmod = sinf((ab * kf) / 22050.0f);
                M = M * (1.0f + mask * band_w[b] * (1.0f + 0.2f * tmod));
            }
    }
    if (k <= g_wmax) {
        float pm1 = 1.0f + g_prog_mean;
        int nw = g_nw;
        for (int w = 0; w < nw; w++)
            if (k >= g_ws[w] && k <= g_we[w]) {
                double dd = (double)(k - g_wh[w]) / 5.0;
                float win = (float)exp(-0.5 * dd * dd);
                M *= (1.0f + freq_w[g_wk[w]] * win * g_wcoef[w] * pm1);
            }
    }
    float2 v = g_A[k];
    g_B[k] = make_float2(v.x * M, v.y * M);
}

__global__ void k_passB() {
    int k = blockIdx.x * 256 + threadIdx.x;
    if (k >= Lt) return;
    float2 xc = g_B[k];
    float m = sqrtf(xc.x * xc.x + xc.y * xc.y);
    float ms;
    if (k == 0 || k == Lt - 1) ms = m;
    else {
        float2 l = g_B[k - 1], r = g_B[k + 1];
        ms = 0.7f * m + 0.15f * sqrtf(l.x*l.x + l.y*l.y) + 0.15f * sqrtf(r.x*r.x + r.y*r.y);
    }
    float2 o;
    if (m > 0.0f) { float sc = ms / m; o = make_float2(xc.x * sc, xc.y * sc); }
    else o = make_float2(ms, 0.0f);
    g_A[k] = o;
    if (k > 0 && k < Lt - 1) g_A[NF - k] = make_float2(o.x, -o.y);
}

__global__ void k_extract() {
    int i = blockIdx.x * 256 + threadIdx.x;
    if (i < Lt) g_base[i] = g_A[i].x * (1.0f / (float)NF);
}

__global__ void k_conv1(const float* __restrict__ w, const float* __restrict__ b) {
    __shared__ float si[520], sw[160], sb[32];
    int tid = threadIdx.x, o0 = blockIdx.x * 256;
    int j0 = 2 * o0 - 2;
    for (int i = tid; i < 516; i += 256) {
        int j = j0 + i;
        si[i] = (j >= 0 && j < Lt) ? g_base[j] : 0.0f;
    }
    if (tid < 160) sw[tid] = w[tid];
    if (tid < 32) sb[tid] = b[tid];
    __syncthreads();
    int o = o0 + tid;
    if (o >= L1n) return;
    float x0 = si[2*tid], x1 = si[2*tid+1], x2 = si[2*tid+2], x3 = si[2*tid+3], x4 = si[2*tid+4];
    #pragma unroll
    for (int c = 0; c < 32; c++) {
        float a = sb[c] + sw[c*5]*x0 + sw[c*5+1]*x1 + sw[c*5+2]*x2 + sw[c*5+3]*x3 + sw[c*5+4]*x4;
        g_h1[(size_t)c * L1n + o] = a > 0.0f ? a : 0.2f * a;
    }
}

__global__ void k_conv2(const float* __restrict__ w, const float* __restrict__ b) {
    extern __shared__ float sm[];
    float* sw = sm;             // 64*161
    float* si = sm + 64 * 161;  // 32*259
    int tid = threadIdx.x;
    for (int i = tid; i < 10240; i += 256) { int c = i / 160, r = i - c * 160; sw[c * 161 + r] = w[i]; }
    int o0 = blockIdx.x * 128, j0 = 2 * o0 - 2;
    for (int ii = tid; ii < 32 * 259; ii += 256) {
        int ic = ii / 259, jj = ii - ic * 259, j = j0 + jj;
        si[ii] = (j >= 0 && j < L1n) ? g_h1[(size_t)ic * L1n + j] : 0.0f;
    }
    __syncthreads();
    int pg = tid & 15, c0 = (tid >> 4) * 4;
    float acc[4][8];
    #pragma unroll
    for (int cc = 0; cc < 4; cc++) { float bb = b[c0+cc];
        #pragma unroll
        for (int pp = 0; pp < 8; pp++) acc[cc][pp] = bb; }
    for (int ic = 0; ic < 32; ic++)
        #pragma unroll
        for (int k = 0; k < 5; k++) {
            float wr[4];
            #pragma unroll
            for (int cc = 0; cc < 4; cc++) wr[cc] = sw[(c0+cc)*161 + ic*5 + k];
            #pragma unroll
            for (int pp = 0; pp < 8; pp++) {
                float iv = si[ic*259 + 2*pg + 32*pp + k];
                #pragma unroll
                for (int cc = 0; cc < 4; cc++) acc[cc][pp] += wr[cc] * iv;
            }
        }
    #pragma unroll
    for (int pp = 0; pp < 8; pp++) {
        int o = o0 + pg + 16 * pp;
        if (o < L2n)
            #pragma unroll
            for (int cc = 0; cc < 4; cc++) {
                float v = acc[cc][pp];
                g_h2[(size_t)(c0+cc) * L2n + o] = v > 0.0f ? v : 0.2f * v;
            }
    }
}

__global__ void k_conv3(const float* __restrict__ w, const float* __restrict__ b) {
    extern __shared__ float sm[];
    float* sw = sm;              // 128*321
    float* si = sm + 128 * 321;  // 64*131
    int tid = threadIdx.x;
    for (int i = tid; i < 40960; i += 256) { int c = i / 320, r = i - c * 320; sw[c * 321 + r] = w[i]; }
    int o0 = blockIdx.x * 64, j0 = 2 * o0 - 2;
    for (int ii = tid; ii < 64 * 131; ii += 256) {
        int ic = ii / 131, jj = ii - ic * 131, j = j0 + jj;
        si[ii] = (j >= 0 && j < L2n) ? g_h2[(size_t)ic * L2n + j] : 0.0f;
    }
    __syncthreads();
    int pg = tid & 7, c0 = (tid >> 3) * 4;
    float acc[4][8];
    #pragma unroll
    for (int cc = 0; cc < 4; cc++) { float bb = b[c0+cc];
        #pragma unroll
        for (int pp = 0; pp < 8; pp++) acc[cc][pp] = bb; }
    for (int ic = 0; ic < 64; ic++)
        #pragma unroll
        for (int k = 0; k < 5; k++) {
            float wr[4];
            #pragma unroll
            for (int cc = 0; cc < 4; cc++) wr[cc] = sw[(c0+cc)*321 + ic*5 + k];
            #pragma unroll
            for (int pp = 0; pp < 8; pp++) {
                float iv = si[ic*131 + 2*pg + 16*pp + k];
                #pragma unroll
                for (int cc = 0; cc < 4; cc++) acc[cc][pp] += wr[cc] * iv;
            }
        }
    float cs[4] = {0.f, 0.f, 0.f, 0.f};
    #pragma unroll
    for (int pp = 0; pp < 8; pp++) {
        int o = o0 + pg + 8 * pp;
        if (o < L3n)
            #pragma unroll
            for (int cc = 0; cc < 4; cc++) {
                float v = acc[cc][pp];
                cs[cc] += (v > 0.0f ? v : 0.2f * v);
            }
    }
    __syncthreads();
    float* sred = sm;  // 128*8
    #pragma unroll
    for (int cc = 0; cc < 4; cc++) sred[(c0+cc)*8 + pg] = cs[cc];
    __syncthreads();
    if (tid < 128) {
        float s = 0.0f;
        #pragma unroll
        for (int g = 0; g < 8; g++) s += sred[tid*8 + g];
        g_part3[(size_t)blockIdx.x * 128 + tid] = s;
    }
}

__global__ void k_feat() {
    int c = blockIdx.x, tid = threadIdx.x;
    __shared__ double sd[256];
    double a = 0.0;
    for (int bi = tid; bi < NB3; bi += 256) a += (double)g_part3[(size_t)bi * 128 + c];
    sd[tid] = a; __syncthreads();
    for (int s = 128; s > 0; s >>= 1) { if (tid < s) sd[tid] += sd[tid + s]; __syncthreads(); }
    if (tid == 0) g_feat[c] = (float)(sd[0] / (double)L3n);
}

__global__ void k_mlp(const float* __restrict__ w1, const float* __restrict__ b1,
                      const float* __restrict__ w2, const float* __restrict__ b2,
                      float* __restrict__ out) {
    __shared__ float sf[128], sred[256];
    int tid = threadIdx.x;
    if (tid < 128) sf[tid] = g_feat[tid];
    __syncthreads();
    float acc = b1[tid];
    for (int i = 0; i < 128; i++) acc += sf[i] * w1[i * 256 + tid];
    acc = acc > 0.0f ? acc : 0.2f * acc;
    sred[tid] = acc * w2[tid];
    __syncthreads();
    for (int s = 128; s > 0; s >>= 1) { if (tid < s) sred[tid] += sred[tid + s]; __syncthreads(); }
    if (tid == 0) out[0] = sred[0] + b2[0];
}

#define CONV2_SMEM ((64*161 + 32*259) * 4)
#define CONV3_SMEM ((128*321 + 64*131) * 4)

extern "C" void kernel_launch(void* const* d_in, const int* in_sizes, int n_in,
                              void* d_out, int out_size) {
    (void)in_sizes; (void)n_in; (void)out_size;
    const float* z   = (const float*)d_in[0];
    const float* bw  = (const float*)d_in[2];
    const float* fw  = (const float*)d_in[3];
    const float* hp  = (const float*)d_in[4];
    const float* tw1 = (const float*)d_in[5];  const float* tb1 = (const float*)d_in[6];
    const float* tw2 = (const float*)d_in[7];  const float* tb2 = (const float*)d_in[8];
    const float* tw3 = (const float*)d_in[9];  const float* tb3 = (const float*)d_in[10];
    const float* c1w = (const float*)d_in[11]; const float* c1b = (const float*)d_in[12];
    const float* c2w = (const float*)d_in[13]; const float* c2b = (const float*)d_in[14];
    const float* c3w = (const float*)d_in[15]; const float* c3b = (const float*)d_in[16];
    const float* mw1 = (const float*)d_in[17]; const float* mb1 = (const float*)d_in[18];
    const float* mw2 = (const float*)d_in[19]; const float* mb2 = (const float*)d_in[20];
    float* out = (float*)d_out;

    cudaFuncSetAttribute(k_conv2, cudaFuncAttributeMaxDynamicSharedMemorySize, CONV2_SMEM);
    cudaFuncSetAttribute(k_conv3, cudaFuncAttributeMaxDynamicSharedMemorySize, CONV3_SMEM);

    k_prep<<<NF / 256, 256>>>(z);
    int src = 1;
    for (int st = 0; st < 22; st++) {
        k_fft<<<NH / 256, 256>>>(src, st, -1.0f, 1.0f / (float)(NF >> st));
        src ^= 1;
    }
    k_prog<<<1024, 256>>>(tw1, tb1, tw2, tb2, tw3, tb3, hp);
    k_progfinal<<<1, 256>>>();
    k_wininit<<<1, 1>>>();
    k_passA<<<(Lt + 255) / 256, 256>>>(bw, fw);
    k_passB<<<(Lt + 255) / 256, 256>>>();
    src = 1;
    for (int st = 0; st < 22; st++) {
        k_fft<<<NH / 256, 256>>>(src, st, +1.0f, 1.0f / (float)(NF >> st));
        src ^= 1;
    }
    k_extract<<<(Lt + 255) / 256, 256>>>();
    k_conv1<<<(L1n + 255) / 256, 256>>>(c1w, c1b);
    k_conv2<<<(L2n + 127) / 128, 256, CONV2_SMEM>>>(c2w, c2b);
    k_conv3<<<(L3n + 63) / 64, 256, CONV3_SMEM>>>(c3w, c3b);
    k_feat<<<128, 256>>>();
    k_mlp<<<1, 256>>>(mw1, mb1, mw2, mb2, out);
}

// round 3
// speedup vs baseline: 1.2196x; 1.2196x over previous
#include <cuda_runtime.h>
#include <math.h>

#define Lt   2097153
#define NF   4194304
#define NQ   1048576
#define L1n  1048577
#define L2n  524289
#define L3n  262145
#define NB3C 1025

typedef unsigned long long u64;

__device__ __forceinline__ u64 pack2(float lo, float hi) {
    u64 r; asm("mov.b64 %0, {%1, %2};" : "=l"(r) : "f"(lo), "f"(hi)); return r;
}
__device__ __forceinline__ void fma2(u64 &acc, u64 a, u64 b) {
    asm("fma.rn.f32x2 %0, %1, %2, %0;" : "+l"(acc) : "l"(a), "l"(b));
}
__device__ __forceinline__ float2 unpack2(u64 v) {
    float2 f; asm("mov.b64 {%0, %1}, %2;" : "=f"(f.x), "=f"(f.y) : "l"(v)); return f;
}

__device__ float2 g_A[NF];
__device__ float2 g_B[NF];
__device__ float  g_base[Lt];
__device__ float  g_h1[33554464];
__device__ float  g_h2[33554496];
__device__ float  g_part3[NB3C * 128];
__device__ float  g_progpart[1024];
__device__ float  g_prog_mean;
__device__ float  g_feat[128];
__device__ int    g_ws[40], g_we[40], g_wh[40], g_wk[40];
__device__ float  g_wcoef[40];
__device__ int    g_nw, g_wmax;

__global__ void k_prep(const float* __restrict__ z) {
    int i = blockIdx.x * 256 + threadIdx.x;
    g_A[i] = make_float2(i < Lt ? z[i] : 0.0f, 0.0f);
}

// Stockham radix-4 stage. s = 4^t, n = NF>>(2t), m = n/4. inv_n = 1/n (exact pow2).
__global__ void k_fft4(int srcA, int t2, float sign, float inv_n) {
    const float2* __restrict__ x = srcA ? g_A : g_B;
    float2* __restrict__ y = srcA ? g_B : g_A;
    int idx = blockIdx.x * 256 + threadIdx.x;   // < NF/4
    int p = idx >> t2;
    int q = idx & ((1 << t2) - 1);
    int s_ = 1 << t2;
    int i0 = q + (p << t2);
    float2 a = x[i0], b = x[i0 + NQ], c = x[i0 + 2*NQ], d = x[i0 + 3*NQ];
    float ang = sign * 6.2831853071795864f * ((float)p * inv_n);
    float sn, cs; sincosf(ang, &sn, &cs);
    float w2r = cs*cs - sn*sn, w2i = 2.0f*cs*sn;
    float w3r = cs*w2r - sn*w2i, w3i = cs*w2i + sn*w2r;
    float apcx = a.x + c.x, apcy = a.y + c.y;
    float amcx = a.x - c.x, amcy = a.y - c.y;
    float bpdx = b.x + d.x, bpdy = b.y + d.y;
    float sjbx = sign * (d.y - b.y), sjby = sign * (b.x - d.x);
    int o0 = q + ((p << t2) << 2);
    y[o0] = make_float2(apcx + bpdx, apcy + bpdy);
    float v1x = amcx + sjbx, v1y = amcy + sjby;
    y[o0 + s_] = make_float2(v1x*cs - v1y*sn, v1x*sn + v1y*cs);
    float v2x = apcx - bpdx, v2y = apcy - bpdy;
    y[o0 + 2*s_] = make_float2(v2x*w2r - v2y*w2i, v2x*w2i + v2y*w2r);
    float v3x = amcx - sjbx, v3y = amcy - sjby;
    y[o0 + 3*s_] = make_float2(v3x*w3r - v3y*w3i, v3x*w3i + v3y*w3r);
}

__global__ void k_prog(const float* __restrict__ w1, const float* __restrict__ b1,
                       const float* __restrict__ w2, const float* __restrict__ b2,
                       const float* __restrict__ w3, const float* __restrict__ b3,
                       const float* __restrict__ harm) {
    __shared__ float sw1[32], sb1[32], sw2[512], sb2[16], sw3[16], shr[8], sred[256];
    int tid = threadIdx.x;
    if (tid < 32) { sw1[tid] = w1[tid]; sb1[tid] = b1[tid]; }
    if (tid < 16) { sb2[tid] = b2[tid]; sw3[tid] = w3[tid * 8 + 1]; }
    for (int i = tid; i < 512; i += 256) sw2[i] = w2[i];
    if (tid < 8) shr[tid] = harm[tid*4] + harm[tid*4+1] + harm[tid*4+2] + harm[tid*4+3];
    __syncthreads();
    float b3_1 = b3[1], acc = 0.0f;
    for (int t = blockIdx.x * 256 + tid; t < Lt; t += 1024 * 256) {
        float tf = (float)t, tn = tf / 2097153.0f;
        float h1r[32];
        #pragma unroll
        for (int j = 0; j < 32; j++) h1r[j] = fmaxf(tn * sw1[j] + sb1[j], 0.0f);
        float mp1 = b3_1;
        #pragma unroll 4
        for (int k = 0; k < 16; k++) {
            float a2 = sb2[k];
            #pragma unroll
            for (int j = 0; j < 32; j++) a2 += h1r[j] * sw2[j * 16 + k];
            mp1 += fmaxf(a2, 0.0f) * sw3[k];
        }
        float sv = 1.0f + mp1 * sinf((6.2831853071795864f * tf) / 2097153.0f);
        int idx = ((int)floorf((tf / 2097153.0f) * 8.0f)) % 8;
        acc += sv * shr[idx];
    }
    sred[tid] = acc; __syncthreads();
    for (int s = 128; s > 0; s >>= 1) { if (tid < s) sred[tid] += sred[tid + s]; __syncthreads(); }
    if (tid == 0) g_progpart[blockIdx.x] = sred[0];
}

__global__ void k_progfinal() {
    __shared__ double sd[256];
    int tid = threadIdx.x; double a = 0.0;
    for (int i = tid; i < 1024; i += 256) a += (double)g_progpart[i];
    sd[tid] = a; __syncthreads();
    for (int s = 128; s > 0; s >>= 1) { if (tid < s) sd[tid] += sd[tid + s]; __syncthreads(); }
    if (tid == 0) g_prog_mean = (float)(sd[0] / (4.0 * 2097153.0));
}

__global__ void k_wininit() {
    const double SPECd[8] = {7.83, 528.0, 396.0, 2.5, 14.1, 432.0, 6.0, 30.0};
    const double val = 1.0 / (4194304.0 * (1.0 / 22050.0));
    int n = 0, wmax = 0;
    for (int k = 0; k < 8; k++)
        for (int m = 1; m <= 5; m++) {
            double hf = SPECd[k] * m;
            if (hf >= 11025.0) continue;
            int i0 = (int)floor(hf / val + 0.5);
            int best = -1; double bd = 1e300;
            for (int i = i0 - 2; i <= i0 + 2; i++) {
                if (i < 0) continue;
                float fr = (float)((double)i * val);
                double d = fabs((double)fr - hf);
                if (d < bd) { bd = d; best = i; }
            }
            int s = best - 15; if (s < 0) s = 0;
            int e = best + 15; if (e > Lt - 1) e = Lt - 1;
            g_ws[n] = s; g_we[n] = e; g_wh[n] = best; g_wk[n] = k;
            g_wcoef[n] = (float)(1.0 / pow((double)m, 1.2));
            if (e > wmax) wmax = e;
            n++;
        }
    g_nw = n; g_wmax = wmax;
}

// reads spectrum from g_B (fwd FFT output), writes multiplied to g_A
__global__ void k_passA(const float* __restrict__ band_w, const float* __restrict__ freq_w) {
    int k = blockIdx.x * 256 + threadIdx.x;
    if (k >= Lt) return;
    float kf = (float)k;
    float f = (float)((double)k * (1.0 / (4194304.0 * (1.0 / 22050.0))));
    float M = 1.0f;
    const float lo[6] = {1.f, 4.f, 8.f, 13.f, 30.f, 100.f};
    const float hi[6] = {4.f, 8.f, 13.f, 30.f, 100.f, 200.f};
    if (f <= 200.0f) {
        #pragma unroll
        for (int b = 0; b < 6; b++)
            if (f >= lo[b] && f <= hi[b]) {
                float c = (lo[b] + hi[b]) * 0.5f, hw = (hi[b] - lo[b]) * 0.25f;
                float d = (f - c) / hw;
                float mask = expf(-0.5f * d * d);
                float ab = (float)(6.283185307179586 * (double)c);
                float tmod = sinf((ab * kf) / 22050.0f);
                M = M * (1.0f + mask * band_w[b] * (1.0f + 0.2f * tmod));
            }
    }
    if (k <= g_wmax) {
        float pm1 = 1.0f + g_prog_mean;
        int nw = g_nw;
        for (int w = 0; w < nw; w++)
            if (k >= g_ws[w] && k <= g_we[w]) {
                double dd = (double)(k - g_wh[w]) / 5.0;
                float win = (float)exp(-0.5 * dd * dd);
                M *= (1.0f + freq_w[g_wk[w]] * win * g_wcoef[w] * pm1);
            }
    }
    float2 v = g_B[k];
    g_A[k] = make_float2(v.x * M, v.y * M);
}

// reads g_A, writes smoothed + Hermitian-filled full spectrum to g_B
__global__ void k_passB() {
    int k = blockIdx.x * 256 + threadIdx.x;
    if (k >= Lt) return;
    float2 xc = g_A[k];
    float m = sqrtf(xc.x * xc.x + xc.y * xc.y);
    float ms;
    if (k == 0 || k == Lt - 1) ms = m;
    else {
        float2 l = g_A[k - 1], r = g_A[k + 1];
        ms = 0.7f * m + 0.15f * sqrtf(l.x*l.x + l.y*l.y) + 0.15f * sqrtf(r.x*r.x + r.y*r.y);
    }
    float2 o;
    if (m > 0.0f) { float sc = ms / m; o = make_float2(xc.x * sc, xc.y * sc); }
    else o = make_float2(ms, 0.0f);
    g_B[k] = o;
    if (k > 0 && k < Lt - 1) g_B[NF - k] = make_float2(o.x, -o.y);
}

__global__ void k_extract() {
    int i = blockIdx.x * 256 + threadIdx.x;
    if (i < Lt) g_base[i] = g_A[i].x * (1.0f / (float)NF);
}

__global__ void k_conv1(const float* __restrict__ w, const float* __restrict__ b) {
    __shared__ float si[520], sw[160], sb[32];
    int tid = threadIdx.x, o0 = blockIdx.x * 256;
    int j0 = 2 * o0 - 2;
    for (int i = tid; i < 516; i += 256) {
        int j = j0 + i;
        si[i] = (j >= 0 && j < Lt) ? g_base[j] : 0.0f;
    }
    if (tid < 160) sw[tid] = w[tid];
    if (tid < 32) sb[tid] = b[tid];
    __syncthreads();
    int o = o0 + tid;
    if (o >= L1n) return;
    float x0 = si[2*tid], x1 = si[2*tid+1], x2 = si[2*tid+2], x3 = si[2*tid+3], x4 = si[2*tid+4];
    #pragma unroll
    for (int c = 0; c < 32; c++) {
        float a = sb[c] + sw[c*5]*x0 + sw[c*5+1]*x1 + sw[c*5+2]*x2 + sw[c*5+3]*x3 + sw[c*5+4]*x4;
        g_h1[(size_t)c * L1n + o] = a > 0.0f ? a : 0.2f * a;
    }
}

// conv2: 32->64, k=5,s=2. Block: 256 positions x 64ch. Thread: 8ch x 8pos, f32x2.
__global__ void __launch_bounds__(256, 2) k_conv2(const float* __restrict__ w, const float* __restrict__ b) {
    extern __shared__ float sm[];
    float* swt = sm;              // [160][68] transposed weights (rows ic*5+k, cols oc)
    float* si  = sm + 160 * 68;   // [32][516]
    int tid = threadIdx.x;
    for (int i = tid; i < 64 * 160; i += 256) {
        int oc = i / 160, r = i - oc * 160;
        swt[r * 68 + oc] = w[i];
    }
    int o0 = blockIdx.x * 256, j0 = 2 * o0 - 2;
    for (int ii = tid; ii < 32 * 516; ii += 256) {
        int ic = ii / 516, jj = ii - ic * 516, j = j0 + jj;
        si[ii] = (j >= 0 && j < L1n) ? g_h1[(size_t)ic * L1n + j] : 0.0f;
    }
    __syncthreads();
    int pg = tid & 31, c0 = (tid >> 5) * 8;
    u64 acc[4][8];
    #pragma unroll
    for (int cp = 0; cp < 4; cp++) {
        u64 bb = pack2(b[c0 + 2*cp], b[c0 + 2*cp + 1]);
        #pragma unroll
        for (int pp = 0; pp < 8; pp++) acc[cp][pp] = bb;
    }
    for (int ic = 0; ic < 32; ic++) {
        const float* sib = si + ic * 516 + 2 * pg;
        const float* swb = swt + ic * 5 * 68 + c0;
        #pragma unroll
        for (int kk = 0; kk < 5; kk += 2) {
            float2 iv[8];
            #pragma unroll
            for (int pp = 0; pp < 8; pp++) iv[pp] = *(const float2*)(sib + 64 * pp + kk);
            #pragma unroll
            for (int dk = 0; dk < 2; dk++) {
                if (kk + dk < 5) {
                    u64 w0 = *(const u64*)(swb + (kk+dk)*68 + 0);
                    u64 w1 = *(const u64*)(swb + (kk+dk)*68 + 2);
                    u64 w2 = *(const u64*)(swb + (kk+dk)*68 + 4);
                    u64 w3 = *(const u64*)(swb + (kk+dk)*68 + 6);
                    #pragma unroll
                    for (int pp = 0; pp < 8; pp++) {
                        float v = dk ? iv[pp].y : iv[pp].x;
                        u64 vv = pack2(v, v);
                        fma2(acc[0][pp], w0, vv);
                        fma2(acc[1][pp], w1, vv);
                        fma2(acc[2][pp], w2, vv);
                        fma2(acc[3][pp], w3, vv);
                    }
                }
            }
        }
    }
    #pragma unroll
    for (int pp = 0; pp < 8; pp++) {
        int o = o0 + pg + 32 * pp;
        if (o < L2n) {
            #pragma unroll
            for (int cp = 0; cp < 4; cp++) {
                float2 v = unpack2(acc[cp][pp]);
                g_h2[(size_t)(c0 + 2*cp)     * L2n + o] = v.x > 0.0f ? v.x : 0.2f * v.x;
                g_h2[(size_t)(c0 + 2*cp + 1) * L2n + o] = v.y > 0.0f ? v.y : 0.2f * v.y;
            }
        }
    }
}

// conv3: 64->128 split into 2 channel-halves (blockIdx.y). Fused leaky + channel sums.
__global__ void __launch_bounds__(256, 1) k_conv3(const float* __restrict__ w, const float* __restrict__ b) {
    extern __shared__ float sm[];
    float* swt = sm;              // [320][68]
    float* si  = sm + 320 * 68;   // [64][516]
    int tid = threadIdx.x, by = blockIdx.y;
    for (int i = tid; i < 64 * 320; i += 256) {
        int oc = i / 320, r = i - oc * 320;
        swt[r * 68 + oc] = w[(size_t)(by * 64 + oc) * 320 + r];
    }
    int o0 = blockIdx.x * 256, j0 = 2 * o0 - 2;
    for (int ii = tid; ii < 64 * 516; ii += 256) {
        int ic = ii / 516, jj = ii - ic * 516, j = j0 + jj;
        si[ii] = (j >= 0 && j < L2n) ? g_h2[(size_t)ic * L2n + j] : 0.0f;
    }
    __syncthreads();
    int pg = tid & 31, c0 = (tid >> 5) * 8;
    u64 acc[4][8];
    #pragma unroll
    for (int cp = 0; cp < 4; cp++) {
        u64 bb = pack2(b[by*64 + c0 + 2*cp], b[by*64 + c0 + 2*cp + 1]);
        #pragma unroll
        for (int pp = 0; pp < 8; pp++) acc[cp][pp] = bb;
    }
    for (int ic = 0; ic < 64; ic++) {
        const float* sib = si + ic * 516 + 2 * pg;
        const float* swb = swt + ic * 5 * 68 + c0;
        #pragma unroll
        for (int kk = 0; kk < 5; kk += 2) {
            float2 iv[8];
            #pragma unroll
            for (int pp = 0; pp < 8; pp++) iv[pp] = *(const float2*)(sib + 64 * pp + kk);
            #pragma unroll
            for (int dk = 0; dk < 2; dk++) {
                if (kk + dk < 5) {
                    u64 w0 = *(const u64*)(swb + (kk+dk)*68 + 0);
                    u64 w1 = *(const u64*)(swb + (kk+dk)*68 + 2);
                    u64 w2 = *(const u64*)(swb + (kk+dk)*68 + 4);
                    u64 w3 = *(const u64*)(swb + (kk+dk)*68 + 6);
                    #pragma unroll
                    for (int pp = 0; pp < 8; pp++) {
                        float v = dk ? iv[pp].y : iv[pp].x;
                        u64 vv = pack2(v, v);
                        fma2(acc[0][pp], w0, vv);
                        fma2(acc[1][pp], w1, vv);
                        fma2(acc[2][pp], w2, vv);
                        fma2(acc[3][pp], w3, vv);
                    }
                }
            }
        }
    }
    float cs[8];
    #pragma unroll
    for (int cc = 0; cc < 8; cc++) cs[cc] = 0.0f;
    #pragma unroll
    for (int pp = 0; pp < 8; pp++) {
        int o = o0 + pg + 32 * pp;
        if (o < L3n) {
            #pragma unroll
            for (int cp = 0; cp < 4; cp++) {
                float2 v = unpack2(acc[cp][pp]);
                cs[2*cp]     += v.x > 0.0f ? v.x : 0.2f * v.x;
                cs[2*cp + 1] += v.y > 0.0f ? v.y : 0.2f * v.y;
            }
        }
    }
    #pragma unroll
    for (int off = 16; off > 0; off >>= 1)
        #pragma unroll
        for (int cc = 0; cc < 8; cc++)
            cs[cc] += __shfl_xor_sync(0xffffffffu, cs[cc], off);
    if (pg == 0)
        #pragma unroll
        for (int cc = 0; cc < 8; cc++)
            g_part3[(size_t)blockIdx.x * 128 + by * 64 + c0 + cc] = cs[cc];
}

__global__ void k_feat() {
    int c = blockIdx.x, tid = threadIdx.x;
    __shared__ double sd[256];
    double a = 0.0;
    for (int bi = tid; bi < NB3C; bi += 256) a += (double)g_part3[(size_t)bi * 128 + c];
    sd[tid] = a; __syncthreads();
    for (int s = 128; s > 0; s >>= 1) { if (tid < s) sd[tid] += sd[tid + s]; __syncthreads(); }
    if (tid == 0) g_feat[c] = (float)(sd[0] / (double)L3n);
}

__global__ void k_mlp(const float* __restrict__ w1, const float* __restrict__ b1,
                      const float* __restrict__ w2, const float* __restrict__ b2,
                      float* __restrict__ out) {
    __shared__ float sf[128], sred[256];
    int tid = threadIdx.x;
    if (tid < 128) sf[tid] = g_feat[tid];
    __syncthreads();
    float acc = b1[tid];
    for (int i = 0; i < 128; i++) acc += sf[i] * w1[i * 256 + tid];
    acc = acc > 0.0f ? acc : 0.2f * acc;
    sred[tid] = acc * w2[tid];
    __syncthreads();
    for (int s = 128; s > 0; s >>= 1) { if (tid < s) sred[tid] += sred[tid + s]; __syncthreads(); }
    if (tid == 0) out[0] = sred[0] + b2[0];
}

#define CONV2_SMEM ((160*68 + 32*516) * 4)
#define CONV3_SMEM ((320*68 + 64*516) * 4)

extern "C" void kernel_launch(void* const* d_in, const int* in_sizes, int n_in,
                              void* d_out, int out_size) {
    (void)in_sizes; (void)n_in; (void)out_size;
    const float* z   = (const float*)d_in[0];
    const float* bw  = (const float*)d_in[2];
    const float* fw  = (const float*)d_in[3];
    const float* hp  = (const float*)d_in[4];
    const float* tw1 = (const float*)d_in[5];  const float* tb1 = (const float*)d_in[6];
    const float* tw2 = (const float*)d_in[7];  const float* tb2 = (const float*)d_in[8];
    const float* tw3 = (const float*)d_in[9];  const float* tb3 = (const float*)d_in[10];
    const float* c1w = (const float*)d_in[11]; const float* c1b = (const float*)d_in[12];
    const float* c2w = (const float*)d_in[13]; const float* c2b = (const float*)d_in[14];
    const float* c3w = (const float*)d_in[15]; const float* c3b = (const float*)d_in[16];
    const float* mw1 = (const float*)d_in[17]; const float* mb1 = (const float*)d_in[18];
    const float* mw2 = (const float*)d_in[19]; const float* mb2 = (const float*)d_in[20];
    float* out = (float*)d_out;

    cudaFuncSetAttribute(k_conv2, cudaFuncAttributeMaxDynamicSharedMemorySize, CONV2_SMEM);
    cudaFuncSetAttribute(k_conv3, cudaFuncAttributeMaxDynamicSharedMemorySize, CONV3_SMEM);

    k_prep<<<NF / 256, 256>>>(z);
    int src = 1;
    for (int t = 0; t < 11; t++) {
        k_fft4<<<NQ / 256, 256>>>(src, 2 * t, -1.0f, 1.0f / (float)(NF >> (2 * t)));
        src ^= 1;
    }
    // spectrum now in g_B
    k_prog<<<1024, 256>>>(tw1, tb1, tw2, tb2, tw3, tb3, hp);
    k_progfinal<<<1, 256>>>();
    k_wininit<<<1, 1>>>();
    k_passA<<<(Lt + 255) / 256, 256>>>(bw, fw);   // g_B -> g_A
    k_passB<<<(Lt + 255) / 256, 256>>>();         // g_A -> g_B (full Hermitian)
    src = 0;                                       // inverse starts from g_B
    for (int t = 0; t < 11; t++) {
        k_fft4<<<NQ / 256, 256>>>(src, 2 * t, +1.0f, 1.0f / (float)(NF >> (2 * t)));
        src ^= 1;
    }
    // time signal now in g_A
    k_extract<<<(Lt + 255) / 256, 256>>>();
    k_conv1<<<(L1n + 255) / 256, 256>>>(c1w, c1b);
    k_conv2<<<(L2n + 255) / 256, 256, CONV2_SMEM>>>(c2w, c2b);
    {
        dim3 g3((L3n + 255) / 256, 2);
        k_conv3<<<g3, 256, CONV3_SMEM>>>(c3w, c3b);
    }
    k_feat<<<128, 256>>>();
    k_mlp<<<1, 256>>>(mw1, mb1, mw2, mb2, out);
}